// round 15
// baseline (speedup 1.0000x reference)
#include <cuda_runtime.h>
#include <cstdint>

// Fully fused Precoding-GNN, R14: R13 base (proven 572us) with
//  - all weights pre-transposed ONCE to gmem (prep kernel);
//  - per-layer weight staging = float4 copies, double-buffered, issued INSIDE
//    the previous layer's FMA-bound edge phase (off the critical path);
//  - bias GEMM in f32x2 with broadcast wmT/wkT pair loads (256 vs 320 instr).
// Hot loops (edge GEMM, msgs, combine) byte-identical to R13.
// One sample per 2-CTA cluster, hidden state resident in SMEM all 5 layers.
// BS=1024, M=64, K=32, D=32. Each CTA owns 32 antennas -> 1024 edges.
// h layout: h[d][e], e = m_loc*32 + k (pitch 1024 floats).

#define NT 512
#define NW 16
#define TP 33  // transposed-table pitch: bank = (d + mk) % 32, conflict-free

typedef unsigned long long ull;

// Pre-transposed weights, 3072 floats per layer:
//  [l*3072 + 0   .. ] wsT[d*32+h]  (L5: packed [d*2+h])
//  [l*3072 + 1024.. ] wmT[d*32+h]  (L5: packed [d*2+h])
//  [l*3072 + 2048.. ] wkT[d*32+h]  (L5: packed [d*2+h])
__device__ __align__(16) float wTg[5 * 3072];

struct SM {
  float h[32 * 1024];      // 131072 B hidden state [d][e]
  float xs[2 * 1024];      //   8192 B layer-1 input [c][e]
  float wbuf[2][3072];     //  24576 B double-buffered {wsT, wmT, wkT}
  float mmT[32 * TP];      //   4224 B msg_m^T [d][m]
  float mkpT[2][32 * TP];  //   8448 B msg_k partial^T [d][k], parity buffered
  float mkcT[32 * TP];     //   4224 B msg_k combined^T [d][k]
  float bm[32 * 34];       //   4352 B Wm@msg_m  [m][h]
  float bk[32 * 34];       //   4352 B Wk@msg_k  [k][h]
  float red[NW];
  float powslot;
};

struct Params {
  const float* x;
  const float* w[15];
  float* out;
};

extern __shared__ __align__(16) char smem_raw[];

__device__ __forceinline__ uint32_t s2u(const void* p) {
  uint32_t a;
  asm("{ .reg .u64 t; cvta.to.shared.u64 t, %1; cvt.u32.u64 %0, t; }"
      : "=r"(a) : "l"(p));
  return a;
}
__device__ __forceinline__ float peer_ldf(const float* p, uint32_t peer) {
  uint32_t ra;
  asm("mapa.shared::cluster.u32 %0, %1, %2;" : "=r"(ra) : "r"(s2u(p)), "r"(peer));
  float v;
  asm volatile("ld.shared::cluster.f32 %0, [%1];" : "=f"(v) : "r"(ra));
  return v;
}
__device__ __forceinline__ void csync() {
  asm volatile("barrier.cluster.arrive.aligned;" ::: "memory");
  asm volatile("barrier.cluster.wait.aligned;" ::: "memory");
}
__device__ __forceinline__ ull pk2(float x, float y) {
  ull r; asm("mov.b64 %0,{%1,%2};" : "=l"(r) : "f"(x), "f"(y)); return r;
}
__device__ __forceinline__ void upk2(ull v, float& x, float& y) {
  asm("mov.b64 {%0,%1},%2;" : "=f"(x), "=f"(y) : "l"(v));
}
__device__ __forceinline__ void fma2(ull& d, ull a, ull b) {
  asm("fma.rn.f32x2 %0,%1,%2,%0;" : "+l"(d) : "l"(a), "l"(b));
}

// ---- prep: transpose all weights once into wTg ----
__global__ void prep_kernel(Params p) {
  int t = threadIdx.x;
  for (int i = t; i < 64; i += NT) {  // layer 1, DIN=2
    int d = i >> 5, hh = i & 31;
    wTg[d * 32 + hh] = p.w[0][hh * 2 + d];
    wTg[1024 + d * 32 + hh] = p.w[1][hh * 2 + d];
    wTg[2048 + d * 32 + hh] = p.w[2][hh * 2 + d];
  }
  for (int l = 1; l < 4; l++)  // layers 2-4, (32,32)
    for (int i = t; i < 1024; i += NT) {
      int d = i >> 5, hh = i & 31;
      wTg[l * 3072 + d * 32 + hh] = p.w[3 * l][hh * 32 + d];
      wTg[l * 3072 + 1024 + d * 32 + hh] = p.w[3 * l + 1][hh * 32 + d];
      wTg[l * 3072 + 2048 + d * 32 + hh] = p.w[3 * l + 2][hh * 32 + d];
    }
  for (int i = t; i < 64; i += NT) {  // layer 5, (2,32), packed stride-2
    int d = i >> 1, hh = i & 1;
    wTg[4 * 3072 + d * 2 + hh] = p.w[12][hh * 32 + d];
    wTg[4 * 3072 + 1024 + d * 2 + hh] = p.w[13][hh * 32 + d];
    wTg[4 * 3072 + 2048 + d * 2 + hh] = p.w[14][hh * 32 + d];
  }
}

// mmT[d][m] = sum_k src[d][m*32+k]  (contiguous float4 loads, 8-lane tree)
// mkpT[d][k] = sum_{m_loc} src[d][m*32+k]  (coalesced lanes, serial over m)
template <int DIN>
__device__ __forceinline__ void msgs(SM* s, const float* src, float* mkpT,
                                     int lane, int wid) {
  for (int r = wid; r < DIN * 8; r += NW) {
    int d = r >> 3, g = r & 7;  // g: group of 4 antennas (128 floats)
    float4 v = *(const float4*)(src + d * 1024 + g * 128 + lane * 4);
    float t = v.x + v.y + v.z + v.w;
    t += __shfl_xor_sync(0xffffffffu, t, 1);
    t += __shfl_xor_sync(0xffffffffu, t, 2);
    t += __shfl_xor_sync(0xffffffffu, t, 4);
    if ((lane & 7) == 0) s->mmT[d * TP + (g * 4 + (lane >> 3))] = t;
  }
  for (int d = wid; d < DIN; d += NW) {
    float t = 0.f;
#pragma unroll
    for (int m2 = 0; m2 < 32; m2++) t += src[d * 1024 + m2 * 32 + lane];
    mkpT[d * TP + lane] = t;  // coalesced, conflict-free
  }
}

// combine: mkcT = mkpT(local) + mkpT(peer); fully coalesced scalar
template <int DIN>
__device__ __forceinline__ void combine_mk(SM* s, const float* mkpT, int tid,
                                           uint32_t peer) {
  for (int i = tid; i < 32 * DIN; i += NT) {
    int d = i >> 5, k = i & 31;  // k = lane -> coalesced
    int off = d * TP + k;
    s->mkcT[off] = mkpT[off] + peer_ldf(mkpT + off, peer);
  }
}

// One GNN layer, DOUT=32, relu. src = xs (L1) or h (L2-4), dest = h in place.
// wb: this layer's staged weights {wsT, wmT, wkT}. During the edge phase the
// NEXT layer's weights are copied gmem->stage_dst (double buffer).
template <int DIN>
__device__ __forceinline__ void layer32(SM* s, const float* src,
                                        const float* wb, float* stage_dst,
                                        const float* stage_src, int par,
                                        int tid, int lane, int wid,
                                        uint32_t peer) {
  const float* wsT = wb;
  const float* wmT = wb + 1024;
  const float* wkT = wb + 2048;
  float* mkpT = s->mkpT[par];

  msgs<DIN>(s, src, mkpT, lane, wid);
  csync();  // mkpT visible cluster-wide; also orders local mmT
  combine_mk<DIN>(s, mkpT, tid, peer);
  __syncthreads();
  // bias GEMMs (f32x2): thread = (mk, h'-pair); tables conflict-free,
  // weight pairs warp-uniform LDS.64 broadcasts.
  {
    const int mk = tid & 31, hh2 = tid >> 5;  // hh2 in [0,16)
    ull tb = 0, tk = 0;
#pragma unroll
    for (int d = 0; d < DIN; d++) {
      float am = s->mmT[d * TP + mk];
      float ak = s->mkcT[d * TP + mk];
      ull wmv = *(const ull*)(wmT + d * 32 + 2 * hh2);
      ull wkv = *(const ull*)(wkT + d * 32 + 2 * hh2);
      fma2(tb, pk2(am, am), wmv);
      fma2(tk, pk2(ak, ak), wkv);
    }
    float a, b;
    upk2(tb, a, b); *(float2*)(s->bm + mk * 34 + 2 * hh2) = make_float2(a, b);
    upk2(tk, a, b); *(float2*)(s->bk + mk * 34 + 2 * hh2) = make_float2(a, b);
  }
  __syncthreads();

  // ---- stage next layer's weights (hidden under the FMA-bound edge loop) ----
  {
    const float4* srcv = (const float4*)stage_src;
    float4* dstv = (float4*)stage_dst;
    for (int i = tid; i < 768; i += NT) dstv[i] = srcv[i];
  }

  // ---- edge GEMM: 2 edges x 32 h' per thread (R3-exact) ----
  const int e0 = 2 * tid, m = e0 >> 5, k0 = e0 & 31;
  ull a0[16], a1[16];
#pragma unroll
  for (int j = 0; j < 16; j++) {
    float2 bmv = *(const float2*)(s->bm + m * 34 + 2 * j);
    float2 b0v = *(const float2*)(s->bk + k0 * 34 + 2 * j);
    float2 b1v = *(const float2*)(s->bk + (k0 + 1) * 34 + 2 * j);
    a0[j] = pk2(bmv.x + b0v.x, bmv.y + b0v.y);
    a1[j] = pk2(bmv.x + b1v.x, bmv.y + b1v.y);
  }
#pragma unroll 4
  for (int d = 0; d < DIN; d++) {
    float2 hv = *(const float2*)(src + d * 1024 + e0);
    ull H0 = pk2(hv.x, hv.x), H1 = pk2(hv.y, hv.y);
    const ulonglong2* wr = (const ulonglong2*)(wsT + d * 32);
#pragma unroll
    for (int q = 0; q < 8; q++) {
      ulonglong2 w = wr[q];  // broadcast LDS.128, used directly (no repack)
      fma2(a0[2 * q], H0, w.x);
      fma2(a0[2 * q + 1], H0, w.y);
      fma2(a1[2 * q], H1, w.x);
      fma2(a1[2 * q + 1], H1, w.y);
    }
  }
  // threads touch only their own 2 columns -> in-place is private, no barrier
#pragma unroll
  for (int j = 0; j < 16; j++) {
    float x0, x1, y0, y1;
    upk2(a0[j], x0, x1);
    upk2(a1[j], y0, y1);
    x0 = fmaxf(x0, 0.f); x1 = fmaxf(x1, 0.f);
    y0 = fmaxf(y0, 0.f); y1 = fmaxf(y1, 0.f);
    *(float2*)(s->h + (2 * j) * 1024 + e0) = make_float2(x0, y0);
    *(float2*)(s->h + (2 * j + 1) * 1024 + e0) = make_float2(x1, y1);
  }
  __syncthreads();  // h + staged weights ready for next layer
}

__global__ void __launch_bounds__(NT, 1) __cluster_dims__(2, 1, 1)
gnn_kernel(Params p) {
  SM* s = (SM*)smem_raw;
  const int tid = threadIdx.x, lane = tid & 31, wid = tid >> 5;
  uint32_t rank;
  asm("mov.u32 %0, %%cluster_ctarank;" : "=r"(rank));
  const uint32_t peer = rank ^ 1u;
  const int sample = blockIdx.x >> 1;

  // stage x -> xs[c][e], and layer-1 weights -> wbuf[0]
  {
    const float* xg = p.x + (size_t)sample * 4096 + (size_t)rank * 2048;
    float4 v = *(const float4*)(xg + 4 * tid);
    int e0 = 2 * tid;
    s->xs[e0] = v.x; s->xs[e0 + 1] = v.z;
    s->xs[1024 + e0] = v.y; s->xs[1024 + e0 + 1] = v.w;
    const float4* srcv = (const float4*)wTg;
    float4* dstv = (float4*)s->wbuf[0];
    for (int i = tid; i < 768; i += NT) dstv[i] = srcv[i];
  }
  __syncthreads();

  // parities: L1:0 L2:1 L3:0 L4:1 L5:0 (overwrite distance 2 => safe)
  // weight buffers: L1:0 L2:1 L3:0 L4:1 L5:0; each layer stages the next.
  layer32<2>(s, s->xs, s->wbuf[0], s->wbuf[1], wTg + 3072, 0, tid, lane, wid,
             peer);
  layer32<32>(s, s->h, s->wbuf[1], s->wbuf[0], wTg + 2 * 3072, 1, tid, lane,
              wid, peer);
  layer32<32>(s, s->h, s->wbuf[0], s->wbuf[1], wTg + 3 * 3072, 0, tid, lane,
              wid, peer);
  layer32<32>(s, s->h, s->wbuf[1], s->wbuf[0], wTg + 4 * 3072, 1, tid, lane,
              wid, peer);

  // ---- layer 5 (DIN=32, DOUT=2, no relu) + power norm + store ----
  {
    const float* wsT5 = s->wbuf[0];         // packed [d*2+h]
    const float* wmT5 = s->wbuf[0] + 1024;  // packed [d*2+h]
    const float* wkT5 = s->wbuf[0] + 2048;
    float* mkpT = s->mkpT[0];
    msgs<32>(s, s->h, mkpT, lane, wid);
    csync();
    combine_mk<32>(s, mkpT, tid, peer);
    __syncthreads();
    if (tid < 32) {  // bias: one mk per thread, both h' via f32x2
      ull tb = 0, tk = 0;
#pragma unroll
      for (int d = 0; d < 32; d++) {
        float am = s->mmT[d * TP + tid];
        float ak = s->mkcT[d * TP + tid];
        ull wmv = *(const ull*)(wmT5 + d * 2);
        ull wkv = *(const ull*)(wkT5 + d * 2);
        fma2(tb, pk2(am, am), wmv);
        fma2(tk, pk2(ak, ak), wkv);
      }
      float a, b;
      upk2(tb, a, b); *(float2*)(s->bm + tid * 34) = make_float2(a, b);
      upk2(tk, a, b); *(float2*)(s->bk + tid * 34) = make_float2(a, b);
    }
    __syncthreads();

    // 2 edges per thread
    const int e0 = 2 * tid, m = e0 >> 5, k0 = e0 & 31;
    float2 bmv = *(const float2*)(s->bm + m * 34);
    float2 b0v = *(const float2*)(s->bk + k0 * 34);
    float2 b1v = *(const float2*)(s->bk + (k0 + 1) * 34);
    ull a0 = pk2(bmv.x + b0v.x, bmv.y + b0v.y);
    ull a1 = pk2(bmv.x + b1v.x, bmv.y + b1v.y);
#pragma unroll 8
    for (int d = 0; d < 32; d++) {
      float2 hv = *(const float2*)(s->h + d * 1024 + e0);
      ull w = *(const ull*)(wsT5 + d * 2);
      fma2(a0, pk2(hv.x, hv.x), w);
      fma2(a1, pk2(hv.y, hv.y), w);
    }
    float x0, x1, y0, y1;
    upk2(a0, x0, x1);
    upk2(a1, y0, y1);

    // power = sum over whole sample of z^2
    float pl = x0 * x0 + x1 * x1 + y0 * y0 + y1 * y1;
    pl += __shfl_xor_sync(0xffffffffu, pl, 1);
    pl += __shfl_xor_sync(0xffffffffu, pl, 2);
    pl += __shfl_xor_sync(0xffffffffu, pl, 4);
    pl += __shfl_xor_sync(0xffffffffu, pl, 8);
    pl += __shfl_xor_sync(0xffffffffu, pl, 16);
    if (lane == 0) s->red[wid] = pl;
    __syncthreads();
    if (tid == 0) {
      float t = 0.f;
#pragma unroll
      for (int w2 = 0; w2 < NW; w2++) t += s->red[w2];
      s->powslot = t;
    }
    csync();  // both CTAs' powslot ready
    float al = rsqrtf(s->powslot + peer_ldf(&s->powslot, peer));  // PT = 1

    float4 o = make_float4(al * x0, al * x1, al * y0, al * y1);
    *(float4*)(p.out + (size_t)sample * 4096 + (size_t)rank * 2048 + 4 * tid) = o;
    csync();  // keep our smem alive until peer finished its powslot read
  }
}

extern "C" void kernel_launch(void* const* d_in, const int* in_sizes, int n_in,
                              void* d_out, int out_size) {
  Params p;
  p.x = (const float*)d_in[0];
  for (int i = 0; i < 15; i++) p.w[i] = (const float*)d_in[1 + i];
  p.out = (float*)d_out;

  prep_kernel<<<1, NT>>>(p);
  cudaFuncSetAttribute(gnn_kernel, cudaFuncAttributeMaxDynamicSharedMemorySize,
                       (int)sizeof(SM));
  gnn_kernel<<<2048, NT, sizeof(SM)>>>(p);
}

// round 17
// speedup vs baseline: 1.2171x; 1.2171x over previous
#include <cuda_runtime.h>
#include <cuda_bf16.h>
#include <cstdint>

// R17: edge GEMM on the tensor pipe via baseline-PTX mma.sync m16n8k16
// (bf16 split hi/lo, fp32 accum). tcgen05 is unavailable: harness compiles
// through compute_103 virtual PTX (no 'a'), which rejects sm_103a-only ops.
// h stored fp32 [e][d] pitch 36 (bank-engineered). Bias folded into C-frag
// init. msgs/combine/bias/L5/power-norm keep the proven R13 structure.
// One sample per 2-CTA cluster. BS=1024, M=64, K=32, D=32; CTA = 32 antennas.

#define NT 512
#define NW 16
#define HP 36  // h pitch (floats): fragment loads <=2-way bank conflicts
#define TP 33  // msg tables [d][*]: conflict-free
#define BP 34  // bias tables [mk][h]: float2-aligned, ~2-way

typedef unsigned long long ull;

// prep outputs: bf16 Ws hi/lo for layers 2-4 + fp32 transposed bias weights
__device__ __align__(16) __nv_bfloat16 wBg[6 * 1024];  // hi0,lo0,hi1,lo1,hi2,lo2
__device__ __align__(16) float wOg[3 * 2048 + 384];    // wmT/wkT L2-4; L1; L5

struct SM {
  float h[1024 * HP];          // 147456 B hidden state [e][d]
  float xs[2 * 1024];          //   8192 B layer-1 input [c][e]
  __nv_bfloat16 wB[6 * 1024];  //  12288 B Ws hi/lo [h*32+d]
  float wMK[3 * 2048];         //  24576 B wmT/wkT [d*32+h] layers 2-4
  float wL1[192];              //    768 B ws/wm/wk T, [d*32+h], d<2
  float wL5[192];              //    768 B packed [d*2+h]
  float mmT[32 * TP];          //   4224 B msg_m^T [d][m]
  float mkpT[2][32 * TP];      //   8448 B msg_k partial^T [d][k]
  float mkcT[32 * TP];         //   4224 B msg_k combined^T [d][k]
  float bm[32 * BP];           //   4352 B bias m [m][h]
  float bk[32 * BP];           //   4352 B bias k [k][h]
  float red[NW];
  float powslot;
};

struct Params {
  const float* x;
  const float* w[15];
  float* out;
};

extern __shared__ __align__(16) char smem_raw[];

__device__ __forceinline__ uint32_t s2u(const void* p) {
  uint32_t a;
  asm("{ .reg .u64 t; cvta.to.shared.u64 t, %1; cvt.u32.u64 %0, t; }"
      : "=r"(a) : "l"(p));
  return a;
}
__device__ __forceinline__ float peer_ldf(const float* p, uint32_t peer) {
  uint32_t ra;
  asm("mapa.shared::cluster.u32 %0, %1, %2;" : "=r"(ra) : "r"(s2u(p)), "r"(peer));
  float v;
  asm volatile("ld.shared::cluster.f32 %0, [%1];" : "=f"(v) : "r"(ra));
  return v;
}
__device__ __forceinline__ void csync() {
  asm volatile("barrier.cluster.arrive.aligned;" ::: "memory");
  asm volatile("barrier.cluster.wait.aligned;" ::: "memory");
}
__device__ __forceinline__ ull pk2(float x, float y) {
  ull r; asm("mov.b64 %0,{%1,%2};" : "=l"(r) : "f"(x), "f"(y)); return r;
}
__device__ __forceinline__ void upk2(ull v, float& x, float& y) {
  asm("mov.b64 {%0,%1},%2;" : "=f"(x), "=f"(y) : "l"(v));
}
__device__ __forceinline__ void fma2(ull& d, ull a, ull b) {
  asm("fma.rn.f32x2 %0,%1,%2,%0;" : "+l"(d) : "l"(a), "l"(b));
}
__device__ __forceinline__ uint32_t bf2(float lo, float hi) {  // low half = lo
  uint32_t r;
  asm("cvt.rn.bf16x2.f32 %0, %1, %2;" : "=r"(r) : "f"(hi), "f"(lo));
  return r;
}
__device__ __forceinline__ float bfr(float x) {
  return __bfloat162float(__float2bfloat16(x));
}
// D += A x B  (m16n8k16 row.col bf16 -> f32)
__device__ __forceinline__ void mma4(float& d0, float& d1, float& d2, float& d3,
                                     const uint32_t* a, const uint32_t* b) {
  asm volatile(
      "mma.sync.aligned.m16n8k16.row.col.f32.bf16.bf16.f32 "
      "{%0,%1,%2,%3},{%4,%5,%6,%7},{%8,%9},{%0,%1,%2,%3};"
      : "+f"(d0), "+f"(d1), "+f"(d2), "+f"(d3)
      : "r"(a[0]), "r"(a[1]), "r"(a[2]), "r"(a[3]), "r"(b[0]), "r"(b[1]));
}

// ---- prep: split-bf16 Ws + transposed bias/L1/L5 weights ----
__global__ void prep_kernel(Params p) {
  int t = threadIdx.x;
  for (int l = 0; l < 3; l++) {
    const float* Ws = p.w[3 * (l + 1)];
    for (int i = t; i < 1024; i += NT) {  // i = h*32+d (natural layout)
      float w = Ws[i];
      __nv_bfloat16 hi = __float2bfloat16(w);
      wBg[(2 * l) * 1024 + i] = hi;
      wBg[(2 * l + 1) * 1024 + i] = __float2bfloat16(w - __bfloat162float(hi));
      int hh = i >> 5, d = i & 31;
      wOg[l * 2048 + d * 32 + hh] = p.w[3 * (l + 1) + 1][i];
      wOg[l * 2048 + 1024 + d * 32 + hh] = p.w[3 * (l + 1) + 2][i];
    }
  }
  for (int i = t; i < 64; i += NT) {  // L1: [d*32+h], d<2
    int d = i >> 5, hh = i & 31;
    wOg[6144 + d * 32 + hh] = p.w[0][hh * 2 + d];
    wOg[6144 + 64 + d * 32 + hh] = p.w[1][hh * 2 + d];
    wOg[6144 + 128 + d * 32 + hh] = p.w[2][hh * 2 + d];
  }
  for (int i = t; i < 64; i += NT) {  // L5 packed [d*2+h]
    int d = i >> 1, hh = i & 1;
    wOg[6336 + d * 2 + hh] = p.w[12][hh * 32 + d];
    wOg[6336 + 64 + d * 2 + hh] = p.w[13][hh * 32 + d];
    wOg[6336 + 128 + d * 2 + hh] = p.w[14][hh * 32 + d];
  }
}

// L1 messages from xs[c][e] (pitch 1024), R13-proven pattern
__device__ __forceinline__ void msgs2(SM* s, float* mkpT, int lane, int wid) {
  {
    int r = wid;  // 16 items: (c, antenna-group)
    int c = r >> 3, g4 = r & 7;
    float4 v = *(const float4*)(s->xs + c * 1024 + g4 * 128 + lane * 4);
    float t = v.x + v.y + v.z + v.w;
    t += __shfl_xor_sync(0xffffffffu, t, 1);
    t += __shfl_xor_sync(0xffffffffu, t, 2);
    t += __shfl_xor_sync(0xffffffffu, t, 4);
    if ((lane & 7) == 0) s->mmT[c * TP + (g4 * 4 + (lane >> 3))] = t;
  }
  if (wid < 2) {
    int d = wid;
    float t = 0.f;
#pragma unroll
    for (int m2 = 0; m2 < 32; m2++) t += s->xs[d * 1024 + m2 * 32 + lane];
    mkpT[d * TP + lane] = t;
  }
}

// messages from h[e][d] (pitch HP); lane = d, conflict-free
__device__ __forceinline__ void msgs32h(SM* s, float* mkpT, int lane, int wid) {
  for (int kk = wid; kk < 32; kk += NW) {
    float t = 0.f;
#pragma unroll
    for (int m2 = 0; m2 < 32; m2++) t += s->h[(m2 * 32 + kk) * HP + lane];
    mkpT[lane * TP + kk] = t;
  }
  for (int mm = wid; mm < 32; mm += NW) {
    float t = 0.f;
#pragma unroll
    for (int k2 = 0; k2 < 32; k2++) t += s->h[(mm * 32 + k2) * HP + lane];
    s->mmT[lane * TP + mm] = t;
  }
}

template <int DIN>
__device__ __forceinline__ void combine_mk(SM* s, const float* mkpT, int tid,
                                           uint32_t peer) {
  for (int i = tid; i < 32 * DIN; i += NT) {
    int d = i >> 5, k = i & 31;
    int off = d * TP + k;
    s->mkcT[off] = mkpT[off] + peer_ldf(mkpT + off, peer);
  }
}

// bias GEMM (f32x2): thread = (mk, h-pair); writes bm/bk pitch BP
template <int DIN>
__device__ __forceinline__ void bias_gemm(SM* s, const float* wmT,
                                          const float* wkT, int tid) {
  const int mk = tid & 31, h2 = tid >> 5;
  ull tb = 0, tk = 0;
#pragma unroll
  for (int d = 0; d < DIN; d++) {
    float am = s->mmT[d * TP + mk];
    float ak = s->mkcT[d * TP + mk];
    ull wmv = *(const ull*)(wmT + d * 32 + 2 * h2);
    ull wkv = *(const ull*)(wkT + d * 32 + 2 * h2);
    fma2(tb, pk2(am, am), wmv);
    fma2(tk, pk2(ak, ak), wkv);
  }
  float a, b;
  upk2(tb, a, b); *(float2*)(s->bm + mk * BP + 2 * h2) = make_float2(a, b);
  upk2(tk, a, b); *(float2*)(s->bk + mk * BP + 2 * h2) = make_float2(a, b);
}

__global__ void __launch_bounds__(NT, 1) __cluster_dims__(2, 1, 1)
gnn_kernel(Params p) {
  SM* s = (SM*)smem_raw;
  const int tid = threadIdx.x, lane = tid & 31, wid = tid >> 5;
  uint32_t rank;
  asm("mov.u32 %0, %%cluster_ctarank;" : "=r"(rank));
  const uint32_t peer = rank ^ 1u;
  const int sample = blockIdx.x >> 1;
  const int g = lane >> 2, tg = lane & 3;

  // ---- one-time staging ----
  {
    const float4* a = (const float4*)wBg;
    float4* b = (float4*)s->wB;
    for (int i = tid; i < 768; i += NT) b[i] = a[i];
    const float4* c = (const float4*)wOg;
    float4* d4 = (float4*)s->wMK;  // wMK+wL1+wL5 contiguous: 6528 fl = 1632 f4
    for (int i = tid; i < 1632; i += NT) d4[i] = c[i];
    const float* xg = p.x + (size_t)sample * 4096 + (size_t)rank * 2048;
    float4 v = *(const float4*)(xg + 4 * tid);
    int e0 = 2 * tid;
    s->xs[e0] = v.x; s->xs[e0 + 1] = v.z;
    s->xs[1024 + e0] = v.y; s->xs[1024 + e0 + 1] = v.w;
  }
  __syncthreads();

  // ================= L1 (scalar, DIN=2) -> h[e][d] =================
  {
    msgs2(s, s->mkpT[0], lane, wid);
    csync();
    combine_mk<2>(s, s->mkpT[0], tid, peer);
    __syncthreads();
    bias_gemm<2>(s, s->wL1 + 64, s->wL1 + 128, tid);
    __syncthreads();
    const float* wsT = s->wL1;  // [d*32+h], d<2
    const int e0 = 2 * tid, m = e0 >> 5, k0 = e0 & 31;
    ull a0[16], a1[16];
#pragma unroll
    for (int j = 0; j < 16; j++) {
      float2 bmv = *(const float2*)(s->bm + m * BP + 2 * j);
      float2 b0v = *(const float2*)(s->bk + k0 * BP + 2 * j);
      float2 b1v = *(const float2*)(s->bk + (k0 + 1) * BP + 2 * j);
      a0[j] = pk2(bmv.x + b0v.x, bmv.y + b0v.y);
      a1[j] = pk2(bmv.x + b1v.x, bmv.y + b1v.y);
    }
#pragma unroll
    for (int d = 0; d < 2; d++) {
      float2 hv = *(const float2*)(s->xs + d * 1024 + e0);
      ull H0 = pk2(hv.x, hv.x), H1 = pk2(hv.y, hv.y);
      const ulonglong2* wr = (const ulonglong2*)(wsT + d * 32);
#pragma unroll
      for (int q = 0; q < 8; q++) {
        ulonglong2 w = wr[q];
        fma2(a0[2 * q], H0, w.x); fma2(a0[2 * q + 1], H0, w.y);
        fma2(a1[2 * q], H1, w.x); fma2(a1[2 * q + 1], H1, w.y);
      }
    }
#pragma unroll
    for (int j = 0; j < 16; j++) {
      float x0, x1, y0, y1;
      upk2(a0[j], x0, x1); upk2(a1[j], y0, y1);
      x0 = fmaxf(x0, 0.f); x1 = fmaxf(x1, 0.f);
      y0 = fmaxf(y0, 0.f); y1 = fmaxf(y1, 0.f);
      *(float2*)(s->h + e0 * HP + 2 * j) = make_float2(x0, x1);
      *(float2*)(s->h + (e0 + 1) * HP + 2 * j) = make_float2(y0, y1);
    }
    __syncthreads();
  }

  // ================= layers 2..4: tensor (mma.sync) =================
  for (int l = 0; l < 3; l++) {
    float* mkpT = s->mkpT[(l + 1) & 1];
    msgs32h(s, mkpT, lane, wid);
    csync();
    combine_mk<32>(s, mkpT, tid, peer);
    __syncthreads();
    bias_gemm<32>(s, s->wMK + l * 2048, s->wMK + l * 2048 + 1024, tid);
    __syncthreads();

    // B fragments (Ws hi/lo), loaded once per layer, register-resident
    const __nv_bfloat16* Whi = s->wB + (2 * l) * 1024;
    const __nv_bfloat16* Wlo = s->wB + (2 * l + 1) * 1024;
    uint32_t bhi[4][2][2], blo[4][2][2];
#pragma unroll
    for (int nt = 0; nt < 4; nt++)
#pragma unroll
      for (int ks = 0; ks < 2; ks++) {
        int base = (nt * 8 + g) * 32 + ks * 16 + 2 * tg;
        bhi[nt][ks][0] = *(const uint32_t*)(Whi + base);
        bhi[nt][ks][1] = *(const uint32_t*)(Whi + base + 8);
        blo[nt][ks][0] = *(const uint32_t*)(Wlo + base);
        blo[nt][ks][1] = *(const uint32_t*)(Wlo + base + 8);
      }
    // 4 m-tiles of 16 edges each (warp owns edges wid*64..+64)
#pragma unroll
    for (int mt = 0; mt < 4; mt++) {
      const int eb = wid * 64 + mt * 16;
      const int m = eb >> 5;
      const int kg = (mt & 1) * 16 + g;
      uint32_t ahi[2][4], alo[2][4];
#pragma unroll
      for (int ks = 0; ks < 2; ks++)
#pragma unroll
        for (int half = 0; half < 2; half++) {
          int c = ks * 16 + half * 8 + 2 * tg;
          float2 v0 = *(const float2*)(s->h + (eb + g) * HP + c);
          float2 v1 = *(const float2*)(s->h + (eb + g + 8) * HP + c);
          ahi[ks][half * 2] = bf2(v0.x, v0.y);
          ahi[ks][half * 2 + 1] = bf2(v1.x, v1.y);
          alo[ks][half * 2] = bf2(v0.x - bfr(v0.x), v0.y - bfr(v0.y));
          alo[ks][half * 2 + 1] = bf2(v1.x - bfr(v1.x), v1.y - bfr(v1.y));
        }
#pragma unroll
      for (int nt = 0; nt < 4; nt++) {
        const int col = nt * 8 + 2 * tg;
        float2 bmv = *(const float2*)(s->bm + m * BP + col);
        float2 bk0 = *(const float2*)(s->bk + kg * BP + col);
        float2 bk1 = *(const float2*)(s->bk + (kg + 8) * BP + col);
        float d0 = bmv.x + bk0.x, d1 = bmv.y + bk0.y;
        float d2 = bmv.x + bk1.x, d3 = bmv.y + bk1.y;
#pragma unroll
        for (int ks = 0; ks < 2; ks++) {
          mma4(d0, d1, d2, d3, ahi[ks], bhi[nt][ks]);
          mma4(d0, d1, d2, d3, ahi[ks], blo[nt][ks]);
          mma4(d0, d1, d2, d3, alo[ks], bhi[nt][ks]);
        }
        d0 = fmaxf(d0, 0.f); d1 = fmaxf(d1, 0.f);
        d2 = fmaxf(d2, 0.f); d3 = fmaxf(d3, 0.f);
        // in-place OK: rows are warp-private, A already in regs for this mt
        *(float2*)(s->h + (eb + g) * HP + col) = make_float2(d0, d1);
        *(float2*)(s->h + (eb + g + 8) * HP + col) = make_float2(d2, d3);
      }
    }
    __syncthreads();
  }

  // ================= L5 (scalar, DOUT=2) + power norm =================
  {
    msgs32h(s, s->mkpT[0], lane, wid);
    csync();
    combine_mk<32>(s, s->mkpT[0], tid, peer);
    __syncthreads();
    const float* ws5 = s->wL5;         // packed [d*2+h]
    const float* wm5 = s->wL5 + 64;
    const float* wk5 = s->wL5 + 128;
    if (tid < 32) {
      ull tb = 0, tk = 0;
#pragma unroll
      for (int d = 0; d < 32; d++) {
        float am = s->mmT[d * TP + tid], ak = s->mkcT[d * TP + tid];
        fma2(tb, pk2(am, am), *(const ull*)(wm5 + d * 2));
        fma2(tk, pk2(ak, ak), *(const ull*)(wk5 + d * 2));
      }
      float a, b;
      upk2(tb, a, b); *(float2*)(s->bm + tid * BP) = make_float2(a, b);
      upk2(tk, a, b); *(float2*)(s->bk + tid * BP) = make_float2(a, b);
    }
    __syncthreads();

    float z[2][2];
    float pl = 0.f;
#pragma unroll
    for (int i = 0; i < 2; i++) {
      const int e = tid + i * 512, m = e >> 5, k = e & 31;
      ull zz = pk2(s->bm[m * BP] + s->bk[k * BP],
                   s->bm[m * BP + 1] + s->bk[k * BP + 1]);
#pragma unroll
      for (int dp = 0; dp < 16; dp++) {
        float2 hv = *(const float2*)(s->h + e * HP + 2 * dp);
        fma2(zz, pk2(hv.x, hv.x), *(const ull*)(ws5 + 4 * dp));
        fma2(zz, pk2(hv.y, hv.y), *(const ull*)(ws5 + 4 * dp + 2));
      }
      upk2(zz, z[i][0], z[i][1]);
      pl += z[i][0] * z[i][0] + z[i][1] * z[i][1];
    }
    pl += __shfl_xor_sync(0xffffffffu, pl, 1);
    pl += __shfl_xor_sync(0xffffffffu, pl, 2);
    pl += __shfl_xor_sync(0xffffffffu, pl, 4);
    pl += __shfl_xor_sync(0xffffffffu, pl, 8);
    pl += __shfl_xor_sync(0xffffffffu, pl, 16);
    if (lane == 0) s->red[wid] = pl;
    __syncthreads();
    if (tid == 0) {
      float t = 0.f;
#pragma unroll
      for (int w2 = 0; w2 < NW; w2++) t += s->red[w2];
      s->powslot = t;
    }
    csync();
    float al = rsqrtf(s->powslot + peer_ldf(&s->powslot, peer));  // PT = 1
    float* og = p.out + (size_t)sample * 4096 + (size_t)rank * 2048;
#pragma unroll
    for (int i = 0; i < 2; i++) {
      const int e = tid + i * 512;
      *(float2*)(og + 2 * e) = make_float2(al * z[i][0], al * z[i][1]);
    }
    csync();  // keep smem alive until peer read powslot
  }
}

extern "C" void kernel_launch(void* const* d_in, const int* in_sizes, int n_in,
                              void* d_out, int out_size) {
  Params p;
  p.x = (const float*)d_in[0];
  for (int i = 0; i < 15; i++) p.w[i] = (const float*)d_in[1 + i];
  p.out = (float*)d_out;
  prep_kernel<<<1, NT>>>(p);
  cudaFuncSetAttribute(gnn_kernel, cudaFuncAttributeMaxDynamicSharedMemorySize,
                       (int)sizeof(SM));
  gnn_kernel<<<2048, NT, sizeof(SM)>>>(p);
}